// round 14
// baseline (speedup 1.0000x reference)
#include <cuda_runtime.h>
#include <math.h>
#include <stdint.h>

#define BATCH 2
#define SEQ   2048
#define NH    16
#define HD    64
#define EMB   1024
#define MTOT  (BATCH*SEQ)

static __device__ float g_q[BATCH*NH*SEQ*HD];
static __device__ float g_k[BATCH*NH*SEQ*HD];
static __device__ float g_v[BATCH*NH*SEQ*HD];
static __device__ float g_rope[SEQ*64];   // [s][0..31]=cos, [s][32..63]=sin

__device__ __forceinline__ uint32_t cvt_tf32(float f) {
    uint32_t r; asm("cvt.rna.tf32.f32 %0, %1;" : "=r"(r) : "f"(f)); return r;
}
__device__ __forceinline__ float f_tf32(float f) { return __uint_as_float(cvt_tf32(f)); }
__device__ __forceinline__ uint32_t fbits(float f) { return __float_as_uint(f); }

__device__ __forceinline__ void mma8(float c[4], const uint32_t a[4], const uint32_t b[2]) {
    asm volatile(
        "mma.sync.aligned.m16n8k8.row.col.f32.tf32.tf32.f32 "
        "{%0,%1,%2,%3}, {%4,%5,%6,%7}, {%8,%9}, {%0,%1,%2,%3};"
        : "+f"(c[0]), "+f"(c[1]), "+f"(c[2]), "+f"(c[3])
        : "r"(a[0]), "r"(a[1]), "r"(a[2]), "r"(a[3]), "r"(b[0]), "r"(b[1]));
}

__device__ __forceinline__ void cp16(uint32_t smem_addr, const void* gptr) {
    asm volatile("cp.async.ca.shared.global [%0], [%1], 16;"
                 :: "r"(smem_addr), "l"(gptr));
}
#define CP_COMMIT() asm volatile("cp.async.commit_group;" ::: "memory")
#define CP_WAIT2()  asm volatile("cp.async.wait_group 2;" ::: "memory")

// ---------------------------------------------------------------------------
// QKV GEMM v6: 128x128 CTA, 256 thr, warp tile 32x64, K-chunks 32.
// 3-stage cp.async pipeline (raw fp32 in smem, stride 36); tf32 rounding at
// fragment load. Fused RoPE epilogue for Q/K.
// ---------------------------------------------------------------------------
__global__ __launch_bounds__(256, 2) void qkv_gemm_mma(
    const float* __restrict__ X,
    const float* __restrict__ Wq, const float* __restrict__ bq,
    const float* __restrict__ Wk, const float* __restrict__ bk,
    const float* __restrict__ Wv, const float* __restrict__ bv)
{
    const float *W, *bias; float* out;
    if (blockIdx.z == 0)      { W = Wq; bias = bq; out = g_q; }
    else if (blockIdx.z == 1) { W = Wk; bias = bk; out = g_k; }
    else                      { W = Wv; bias = bv; out = g_v; }
    const bool do_rope = (blockIdx.z != 2);

    extern __shared__ float sh[];
    float* As[3] = { sh,         sh + 4608,  sh + 9216 };
    float* Bs[3] = { sh + 13824, sh + 18432, sh + 23040 };

    const int tid  = threadIdx.x;
    const int lane = tid & 31;
    const int wid  = tid >> 5;
    const int gid  = lane >> 2;
    const int tig  = lane & 3;
    const int wm   = wid & 3;
    const int wn   = wid >> 2;
    const int m0 = blockIdx.y * 128;
    const int n0 = blockIdx.x * 128;

    const int lr = tid >> 1;
    const int lc = (tid & 1) * 16;
    const float* ag = X + (size_t)(m0 + lr) * EMB + lc;
    const float* bg = W + (size_t)(n0 + lr) * EMB + lc;

    uint32_t sa[3], sb[3];
    #pragma unroll
    for (int s = 0; s < 3; s++) {
        sa[s] = (uint32_t)__cvta_generic_to_shared(&As[s][lr*36 + lc]);
        sb[s] = (uint32_t)__cvta_generic_to_shared(&Bs[s][lr*36 + lc]);
    }

    float acc[2][8][4];
    #pragma unroll
    for (int i = 0; i < 2; i++)
        #pragma unroll
        for (int t = 0; t < 8; t++)
            #pragma unroll
            for (int e = 0; e < 4; e++) acc[i][t][e] = 0.f;

    // prologue: chunks 0,1,2 in flight
    #pragma unroll
    for (int s = 0; s < 3; s++) {
        #pragma unroll
        for (int j = 0; j < 4; j++) {
            cp16(sa[s] + j*16, ag + s*32 + j*4);
            cp16(sb[s] + j*16, bg + s*32 + j*4);
        }
        CP_COMMIT();
    }

    int buf = 0;
    for (int c = 0; c < 32; c++) {
        CP_WAIT2();
        __syncthreads();

        const float* A = As[buf];
        const float* B = Bs[buf];
        #pragma unroll
        for (int k8 = 0; k8 < 4; k8++) {
            const int kc = k8 * 8 + tig;
            uint32_t a[2][4];
            #pragma unroll
            for (int i = 0; i < 2; i++) {
                const int r = wm * 32 + i * 16 + gid;
                a[i][0] = cvt_tf32(A[r * 36 + kc]);
                a[i][1] = cvt_tf32(A[(r + 8) * 36 + kc]);
                a[i][2] = cvt_tf32(A[r * 36 + kc + 4]);
                a[i][3] = cvt_tf32(A[(r + 8) * 36 + kc + 4]);
            }
            uint32_t b[8][2];
            #pragma unroll
            for (int t = 0; t < 8; t++) {
                const int n = wn * 64 + t * 8 + gid;
                b[t][0] = cvt_tf32(B[n * 36 + kc]);
                b[t][1] = cvt_tf32(B[n * 36 + kc + 4]);
            }
            #pragma unroll
            for (int i = 0; i < 2; i++)
                #pragma unroll
                for (int t = 0; t < 8; t++)
                    mma8(acc[i][t], a[i], b[t]);
        }
        __syncthreads();
        if (c < 29) {
            const int nc = (c + 3) * 32;
            #pragma unroll
            for (int j = 0; j < 4; j++) {
                cp16(sa[buf] + j*16, ag + nc + j*4);
                cp16(sb[buf] + j*16, bg + nc + j*4);
            }
        }
        CP_COMMIT();
        buf = (buf == 2) ? 0 : buf + 1;
    }

    // ---- Epilogue (bias + fused RoPE for Q/K) ----
    if (do_rope) {
        #pragma unroll
        for (int i = 0; i < 2; i++) {
            const int m = m0 + wm * 32 + i * 16 + gid;
            const int bb = m >> 11;
            const int s  = m & 2047;
            const float* rp0 = &g_rope[(size_t)s * 64];
            const float* rp1 = &g_rope[(size_t)(s + 8) * 64];
            #pragma unroll
            for (int t = 0; t < 4; t++) {
                const int n  = n0 + wn * 64 + t * 8 + 2 * tig;   // dd < 32
                const int h  = n >> 6, dd = n & 63;
                const float bl0 = bias[n],      bl1 = bias[n + 1];
                const float bh0 = bias[n + 32], bh1 = bias[n + 33];
                const float lo0 = acc[i][t][0] + bl0,   lo1 = acc[i][t][1] + bl1;
                const float hi0 = acc[i][t+4][0] + bh0, hi1 = acc[i][t+4][1] + bh1;
                const float c0 = rp0[dd], c1 = rp0[dd + 1];
                const float s0 = rp0[32 + dd], s1 = rp0[32 + dd + 1];
                float* po = &out[(((size_t)(bb * NH + h)) * SEQ + s) * HD + dd];
                *(float2*)po        = make_float2(lo0 * c0 - hi0 * s0, lo1 * c1 - hi1 * s1);
                *(float2*)(po + 32) = make_float2(hi0 * c0 + lo0 * s0, hi1 * c1 + lo1 * s1);
                const float lo2 = acc[i][t][2] + bl0,   lo3 = acc[i][t][3] + bl1;
                const float hi2 = acc[i][t+4][2] + bh0, hi3 = acc[i][t+4][3] + bh1;
                const float d0 = rp1[dd], d1 = rp1[dd + 1];
                const float e0 = rp1[32 + dd], e1 = rp1[32 + dd + 1];
                float* po2 = po + 8 * HD;
                *(float2*)po2        = make_float2(lo2 * d0 - hi2 * e0, lo3 * d1 - hi3 * e1);
                *(float2*)(po2 + 32) = make_float2(hi2 * d0 + lo2 * e0, hi3 * d1 + lo3 * e1);
            }
        }
    } else {
        #pragma unroll
        for (int i = 0; i < 2; i++) {
            const int m = m0 + wm * 32 + i * 16 + gid;
            const int bb = m >> 11;
            const int s  = m & 2047;
            #pragma unroll
            for (int t = 0; t < 8; t++) {
                const int n = n0 + wn * 64 + t * 8 + 2 * tig;
                const int h = n >> 6, dd = n & 63;
                const float b0v = bias[n], b1v = bias[n + 1];
                float* po = &out[(((size_t)(bb * NH + h)) * SEQ + s) * HD + dd];
                *(float2*)po = make_float2(acc[i][t][0] + b0v, acc[i][t][1] + b1v);
                float* po2 = po + 8 * HD;
                *(float2*)po2 = make_float2(acc[i][t][2] + b0v, acc[i][t][3] + b1v);
            }
        }
    }
}

// ---------------------------------------------------------------------------
// RoPE table build.
// ---------------------------------------------------------------------------
__global__ void rope_table()
{
    int idx = blockIdx.x * blockDim.x + threadIdx.x;
    if (idx >= SEQ * 32) return;
    const int s = idx >> 5, i = idx & 31;
    const float inv = expf(-(float)i * (logf(10000.0f) / 32.0f));
    float sn, cs;
    sincosf((float)s * inv, &sn, &cs);
    g_rope[s * 64 + i]      = cs;
    g_rope[s * 64 + 32 + i] = sn;
}

// ---------------------------------------------------------------------------
// Flash attention v5 (R12-proven, RESTORED): CTA = (b, h, 128 q-rows),
// 256 thr / 8 warps, warp tile 16x64. No-max softmax, register-prefetched
// K/V, scalar smem (stride 68).
// ---------------------------------------------------------------------------
__global__ __launch_bounds__(256, 2) void flash_mma(const float* __restrict__ mask,
                                                    float* __restrict__ out)
{
    extern __shared__ float sh[];
    float* Qs  = sh;            // 8704
    float* Ks  = sh + 8704;     // 4352
    float* VT  = sh + 13056;    // 4352
    float* Ps  = sh + 17408;    // 8704
    float* msk = sh + 26112;    // 64

    const int tid  = threadIdx.x;
    const int lane = tid & 31;
    const int wid  = tid >> 5;
    const int gid  = lane >> 2;
    const int tig  = lane & 3;
    const int r0   = wid * 16;
    const int q0 = blockIdx.x * 128;
    const int h  = blockIdx.y;
    const int b  = blockIdx.z;

    const size_t hbase = ((size_t)(b*NH + h)) * SEQ * HD;
    const float* qg = g_q + hbase;
    const float* kg = g_k + hbase;
    const float* vg = g_v + hbase;
    const float* mp = mask + (size_t)b * SEQ;

    const int krow = tid >> 2;
    const int koff = (tid & 3) * 16;
    const int vs  = (tid & 31) + 32 * ((tid >> 5) & 1);
    const int vd0 = (tid >> 6) * 16;

    {
        const int qr = tid >> 1;
        const int qc = (tid & 1) * 32;
        const float* qp = qg + (size_t)(q0 + qr) * HD + qc;
        #pragma unroll
        for (int j = 0; j < 8; j++) {
            float4 v = *(const float4*)(qp + j * 4);
            float* p = &Qs[qr * 68 + qc + j * 4];
            p[0]=f_tf32(v.x); p[1]=f_tf32(v.y); p[2]=f_tf32(v.z); p[3]=f_tf32(v.w);
        }
    }

    float4 kr[4], vr[4];
    float mkr;
    #pragma unroll
    for (int j = 0; j < 4; j++) {
        kr[j] = *(const float4*)(kg + (size_t)krow * HD + koff + j * 4);
        vr[j] = *(const float4*)(vg + (size_t)vs * HD + vd0 + j * 4);
    }
    mkr = (tid < 64) ? mp[tid] : 0.f;

    float co[8][4];
    #pragma unroll
    for (int t = 0; t < 8; t++)
        #pragma unroll
        for (int e = 0; e < 4; e++) co[t][e] = 0.f;
    float lR[2] = { 0.f, 0.f };

    for (int t = 0; t < 32; t++) {
        const int tn = (t < 31) ? t + 1 : 31;
        __syncthreads();

        #pragma unroll
        for (int j = 0; j < 4; j++) {
            float* p = &Ks[krow * 68 + koff + j * 4];
            p[0]=f_tf32(kr[j].x); p[1]=f_tf32(kr[j].y); p[2]=f_tf32(kr[j].z); p[3]=f_tf32(kr[j].w);
        }
        #pragma unroll
        for (int j = 0; j < 4; j++) {
            VT[(vd0 + j*4 + 0) * 68 + vs] = f_tf32(vr[j].x);
            VT[(vd0 + j*4 + 1) * 68 + vs] = f_tf32(vr[j].y);
            VT[(vd0 + j*4 + 2) * 68 + vs] = f_tf32(vr[j].z);
            VT[(vd0 + j*4 + 3) * 68 + vs] = f_tf32(vr[j].w);
        }
        if (tid < 64) msk[tid] = mkr;
        __syncthreads();

        #pragma unroll
        for (int j = 0; j < 4; j++)
            kr[j] = *(const float4*)(kg + (size_t)(tn*64 + krow) * HD + koff + j * 4);
        mkr = (tid < 64) ? mp[tn*64 + tid] : 0.f;

        // ---- S = Q K^T ----
        float cs[8][4];
        #pragma unroll
        for (int tt = 0; tt < 8; tt++)
            #pragma unroll
            for (int e = 0; e < 4; e++) cs[tt][e] = 0.f;
        #pragma unroll
        for (int k8 = 0; k8 < 8; k8++) {
            const int kc = k8 * 8 + tig;
            uint32_t a[4];
            a[0] = fbits(Qs[(r0 + gid) * 68 + kc]);
            a[1] = fbits(Qs[(r0 + 8 + gid) * 68 + kc]);
            a[2] = fbits(Qs[(r0 + gid) * 68 + kc + 4]);
            a[3] = fbits(Qs[(r0 + 8 + gid) * 68 + kc + 4]);
            uint32_t bf[8][2];
            #pragma unroll
            for (int tt = 0; tt < 8; tt++) {
                const int n = tt * 8 + gid;
                bf[tt][0] = fbits(Ks[n * 68 + kc]);
                bf[tt][1] = fbits(Ks[n * 68 + kc + 4]);
            }
            #pragma unroll
            for (int tt = 0; tt < 8; tt++)
                mma8(cs[tt], a, bf[tt]);
        }

        // ---- softmax numerator (no max shift; scores bounded) ----
        #pragma unroll
        for (int j = 0; j < 2; j++) {
            const int rbase = r0 + j * 8 + gid;
            #pragma unroll
            for (int tt = 0; tt < 8; tt++) {
                float p0 = __expf(fmaf(cs[tt][j*2],   0.125f, msk[tt*8 + 2*tig]));
                float p1 = __expf(fmaf(cs[tt][j*2+1], 0.125f, msk[tt*8 + 2*tig + 1]));
                lR[j] += p0 + p1;
                *(float2*)&Ps[rbase * 68 + tt * 8 + 2 * tig] =
                    make_float2(f_tf32(p0), f_tf32(p1));
            }
        }

        #pragma unroll
        for (int j = 0; j < 4; j++)
            vr[j] = *(const float4*)(vg + (size_t)(tn*64 + vs) * HD + vd0 + j * 4);

        __syncwarp();

        // ---- O += P V ----
        #pragma unroll
        for (int k8 = 0; k8 < 8; k8++) {
            const int kc = k8 * 8 + tig;
            uint32_t a[4];
            a[0] = fbits(Ps[(r0 + gid) * 68 + kc]);
            a[1] = fbits(Ps[(r0 + 8 + gid) * 68 + kc]);
            a[2] = fbits(Ps[(r0 + gid) * 68 + kc + 4]);
            a[3] = fbits(Ps[(r0 + 8 + gid) * 68 + kc + 4]);
            uint32_t bf[8][2];
            #pragma unroll
            for (int tt = 0; tt < 8; tt++) {
                const int n = tt * 8 + gid;
                bf[tt][0] = fbits(VT[n * 68 + kc]);
                bf[tt][1] = fbits(VT[n * 68 + kc + 4]);
            }
            #pragma unroll
            for (int tt = 0; tt < 8; tt++)
                mma8(co[tt], a, bf[tt]);
        }
    }

    #pragma unroll
    for (int j = 0; j < 2; j++) {
        lR[j] += __shfl_xor_sync(0xffffffffu, lR[j], 1);
        lR[j] += __shfl_xor_sync(0xffffffffu, lR[j], 2);
        const float invl = 1.0f / lR[j];
        const int row = r0 + j * 8 + gid;
        const int s = q0 + row;
        float* po = &out[((size_t)(b * SEQ + s)) * EMB + h * HD];
        #pragma unroll
        for (int tt = 0; tt < 8; tt++) {
            *(float2*)(po + tt * 8 + 2 * tig) =
                make_float2(co[tt][j*2] * invl, co[tt][j*2+1] * invl);
        }
    }
}

// ---------------------------------------------------------------------------
extern "C" void kernel_launch(void* const* d_in, const int* in_sizes, int n_in,
                              void* d_out, int out_size)
{
    const float* x    = (const float*)d_in[0];
    const float* mask = (const float*)d_in[1];
    const float* Wq   = (const float*)d_in[2];
    const float* bq   = (const float*)d_in[3];
    const float* Wk   = (const float*)d_in[4];
    const float* bk   = (const float*)d_in[5];
    const float* Wv   = (const float*)d_in[6];
    const float* bv   = (const float*)d_in[7];
    float* out = (float*)d_out;

    const int gemm_smem  = 27648 * (int)sizeof(float);   // 110592 B
    const int flash_smem = 26176 * (int)sizeof(float);   // 104704 B
    cudaFuncSetAttribute(qkv_gemm_mma, cudaFuncAttributeMaxDynamicSharedMemorySize, gemm_smem);
    cudaFuncSetAttribute(flash_mma,    cudaFuncAttributeMaxDynamicSharedMemorySize, flash_smem);

    rope_table<<<(SEQ*32 + 255)/256, 256>>>();

    dim3 ggrid(EMB/128, MTOT/128, 3);
    qkv_gemm_mma<<<ggrid, 256, gemm_smem>>>(x, Wq, bq, Wk, bk, Wv, bv);

    dim3 fgrid(SEQ/128, NH, BATCH);
    flash_mma<<<fgrid, 256, flash_smem>>>(mask, out);
}

// round 15
// speedup vs baseline: 1.1218x; 1.1218x over previous
#include <cuda_runtime.h>
#include <math.h>
#include <stdint.h>

#define BATCH 2
#define SEQ   2048
#define NH    16
#define HD    64
#define EMB   1024
#define MTOT  (BATCH*SEQ)

static __device__ float g_q[BATCH*NH*SEQ*HD];
static __device__ float g_k[BATCH*NH*SEQ*HD];
static __device__ float g_v[BATCH*NH*SEQ*HD];
static __device__ float g_rope[SEQ*64];   // [s][0..31]=cos, [s][32..63]=sin

__device__ __forceinline__ uint32_t cvt_tf32(float f) {
    uint32_t r; asm("cvt.rna.tf32.f32 %0, %1;" : "=r"(r) : "f"(f)); return r;
}
__device__ __forceinline__ float f_tf32(float f) { return __uint_as_float(cvt_tf32(f)); }
__device__ __forceinline__ uint32_t fbits(float f) { return __float_as_uint(f); }

__device__ __forceinline__ void mma8(float c[4], const uint32_t a[4], const uint32_t b[2]) {
    asm volatile(
        "mma.sync.aligned.m16n8k8.row.col.f32.tf32.tf32.f32 "
        "{%0,%1,%2,%3}, {%4,%5,%6,%7}, {%8,%9}, {%0,%1,%2,%3};"
        : "+f"(c[0]), "+f"(c[1]), "+f"(c[2]), "+f"(c[3])
        : "r"(a[0]), "r"(a[1]), "r"(a[2]), "r"(a[3]), "r"(b[0]), "r"(b[1]));
}

__device__ __forceinline__ void cp16(uint32_t smem_addr, const void* gptr) {
    asm volatile("cp.async.ca.shared.global [%0], [%1], 16;"
                 :: "r"(smem_addr), "l"(gptr));
}
#define CP_COMMIT() asm volatile("cp.async.commit_group;" ::: "memory")
#define CP_WAIT1()  asm volatile("cp.async.wait_group 1;" ::: "memory")

// ---------------------------------------------------------------------------
// QKV GEMM v5 (R12-proven): 128x128 CTA, 256 thr, warp tile 32x64,
// K-chunks 32. 2-stage cp.async pipeline (raw fp32 in smem, stride 36);
// tf32 rounding at fragment load. Fused RoPE epilogue for Q/K.
// smem 73728 B -> 2 CTAs/SM.
// ---------------------------------------------------------------------------
__global__ __launch_bounds__(256, 2) void qkv_gemm_mma(
    const float* __restrict__ X,
    const float* __restrict__ Wq, const float* __restrict__ bq,
    const float* __restrict__ Wk, const float* __restrict__ bk,
    const float* __restrict__ Wv, const float* __restrict__ bv)
{
    const float *W, *bias; float* out;
    if (blockIdx.z == 0)      { W = Wq; bias = bq; out = g_q; }
    else if (blockIdx.z == 1) { W = Wk; bias = bk; out = g_k; }
    else                      { W = Wv; bias = bv; out = g_v; }
    const bool do_rope = (blockIdx.z != 2);

    extern __shared__ float sh[];
    float* As[2] = { sh,        sh + 4608 };
    float* Bs[2] = { sh + 9216, sh + 13824 };

    const int tid  = threadIdx.x;
    const int lane = tid & 31;
    const int wid  = tid >> 5;
    const int gid  = lane >> 2;
    const int tig  = lane & 3;
    const int wm   = wid & 3;
    const int wn   = wid >> 2;
    const int m0 = blockIdx.y * 128;
    const int n0 = blockIdx.x * 128;

    const int lr = tid >> 1;
    const int lc = (tid & 1) * 16;
    const float* ag = X + (size_t)(m0 + lr) * EMB + lc;
    const float* bg = W + (size_t)(n0 + lr) * EMB + lc;

    const uint32_t sa[2] = { (uint32_t)__cvta_generic_to_shared(&As[0][lr*36 + lc]),
                             (uint32_t)__cvta_generic_to_shared(&As[1][lr*36 + lc]) };
    const uint32_t sb[2] = { (uint32_t)__cvta_generic_to_shared(&Bs[0][lr*36 + lc]),
                             (uint32_t)__cvta_generic_to_shared(&Bs[1][lr*36 + lc]) };

    float acc[2][8][4];
    #pragma unroll
    for (int i = 0; i < 2; i++)
        #pragma unroll
        for (int t = 0; t < 8; t++)
            #pragma unroll
            for (int e = 0; e < 4; e++) acc[i][t][e] = 0.f;

    // prologue: chunks 0,1 in flight
    #pragma unroll
    for (int j = 0; j < 4; j++) {
        cp16(sa[0] + j*16, ag + j*4);
        cp16(sb[0] + j*16, bg + j*4);
    }
    CP_COMMIT();
    #pragma unroll
    for (int j = 0; j < 4; j++) {
        cp16(sa[1] + j*16, ag + 32 + j*4);
        cp16(sb[1] + j*16, bg + 32 + j*4);
    }
    CP_COMMIT();

    for (int c = 0; c < 32; c++) {
        const int buf = c & 1;
        CP_WAIT1();
        __syncthreads();

        const float* A = As[buf];
        const float* B = Bs[buf];
        #pragma unroll
        for (int k8 = 0; k8 < 4; k8++) {
            const int kc = k8 * 8 + tig;
            uint32_t a[2][4];
            #pragma unroll
            for (int i = 0; i < 2; i++) {
                const int r = wm * 32 + i * 16 + gid;
                a[i][0] = cvt_tf32(A[r * 36 + kc]);
                a[i][1] = cvt_tf32(A[(r + 8) * 36 + kc]);
                a[i][2] = cvt_tf32(A[r * 36 + kc + 4]);
                a[i][3] = cvt_tf32(A[(r + 8) * 36 + kc + 4]);
            }
            uint32_t b[8][2];
            #pragma unroll
            for (int t = 0; t < 8; t++) {
                const int n = wn * 64 + t * 8 + gid;
                b[t][0] = cvt_tf32(B[n * 36 + kc]);
                b[t][1] = cvt_tf32(B[n * 36 + kc + 4]);
            }
            #pragma unroll
            for (int i = 0; i < 2; i++)
                #pragma unroll
                for (int t = 0; t < 8; t++)
                    mma8(acc[i][t], a[i], b[t]);
        }
        __syncthreads();
        if (c < 30) {
            const int nc = (c + 2) * 32;
            #pragma unroll
            for (int j = 0; j < 4; j++) {
                cp16(sa[buf] + j*16, ag + nc + j*4);
                cp16(sb[buf] + j*16, bg + nc + j*4);
            }
        }
        CP_COMMIT();   // empty groups near the tail keep accounting aligned
    }

    // ---- Epilogue (bias + fused RoPE for Q/K) ----
    if (do_rope) {
        #pragma unroll
        for (int i = 0; i < 2; i++) {
            const int m = m0 + wm * 32 + i * 16 + gid;
            const int bb = m >> 11;
            const int s  = m & 2047;
            const float* rp0 = &g_rope[(size_t)s * 64];
            const float* rp1 = &g_rope[(size_t)(s + 8) * 64];
            #pragma unroll
            for (int t = 0; t < 4; t++) {
                const int n  = n0 + wn * 64 + t * 8 + 2 * tig;   // dd < 32
                const int h  = n >> 6, dd = n & 63;
                const float bl0 = bias[n],      bl1 = bias[n + 1];
                const float bh0 = bias[n + 32], bh1 = bias[n + 33];
                const float lo0 = acc[i][t][0] + bl0,   lo1 = acc[i][t][1] + bl1;
                const float hi0 = acc[i][t+4][0] + bh0, hi1 = acc[i][t+4][1] + bh1;
                const float c0 = rp0[dd], c1 = rp0[dd + 1];
                const float s0 = rp0[32 + dd], s1 = rp0[32 + dd + 1];
                float* po = &out[(((size_t)(bb * NH + h)) * SEQ + s) * HD + dd];
                *(float2*)po        = make_float2(lo0 * c0 - hi0 * s0, lo1 * c1 - hi1 * s1);
                *(float2*)(po + 32) = make_float2(hi0 * c0 + lo0 * s0, hi1 * c1 + lo1 * s1);
                const float lo2 = acc[i][t][2] + bl0,   lo3 = acc[i][t][3] + bl1;
                const float hi2 = acc[i][t+4][2] + bh0, hi3 = acc[i][t+4][3] + bh1;
                const float d0 = rp1[dd], d1 = rp1[dd + 1];
                const float e0 = rp1[32 + dd], e1 = rp1[32 + dd + 1];
                float* po2 = po + 8 * HD;
                *(float2*)po2        = make_float2(lo2 * d0 - hi2 * e0, lo3 * d1 - hi3 * e1);
                *(float2*)(po2 + 32) = make_float2(hi2 * d0 + lo2 * e0, hi3 * d1 + lo3 * e1);
            }
        }
    } else {
        #pragma unroll
        for (int i = 0; i < 2; i++) {
            const int m = m0 + wm * 32 + i * 16 + gid;
            const int bb = m >> 11;
            const int s  = m & 2047;
            #pragma unroll
            for (int t = 0; t < 8; t++) {
                const int n = n0 + wn * 64 + t * 8 + 2 * tig;
                const int h = n >> 6, dd = n & 63;
                const float b0v = bias[n], b1v = bias[n + 1];
                float* po = &out[(((size_t)(bb * NH + h)) * SEQ + s) * HD + dd];
                *(float2*)po = make_float2(acc[i][t][0] + b0v, acc[i][t][1] + b1v);
                float* po2 = po + 8 * HD;
                *(float2*)po2 = make_float2(acc[i][t][2] + b0v, acc[i][t][3] + b1v);
            }
        }
    }
}

// ---------------------------------------------------------------------------
// RoPE table build.
// ---------------------------------------------------------------------------
__global__ void rope_table()
{
    int idx = blockIdx.x * blockDim.x + threadIdx.x;
    if (idx >= SEQ * 32) return;
    const int s = idx >> 5, i = idx & 31;
    const float inv = expf(-(float)i * (logf(10000.0f) / 32.0f));
    float sn, cs;
    sincosf((float)s * inv, &sn, &cs);
    g_rope[s * 64 + i]      = cs;
    g_rope[s * 64 + 32 + i] = sn;
}

// ---------------------------------------------------------------------------
// Flash attention v5 (R12-proven): CTA = (b, h, 128 q-rows), 256 thr / 8
// warps, warp tile 16x64. No-max softmax (scores bounded), register-
// prefetched K/V, scalar smem (stride 68).
// ---------------------------------------------------------------------------
__global__ __launch_bounds__(256, 2) void flash_mma(const float* __restrict__ mask,
                                                    float* __restrict__ out)
{
    extern __shared__ float sh[];
    float* Qs  = sh;            // 8704
    float* Ks  = sh + 8704;     // 4352
    float* VT  = sh + 13056;    // 4352
    float* Ps  = sh + 17408;    // 8704
    float* msk = sh + 26112;    // 64

    const int tid  = threadIdx.x;
    const int lane = tid & 31;
    const int wid  = tid >> 5;
    const int gid  = lane >> 2;
    const int tig  = lane & 3;
    const int r0   = wid * 16;
    const int q0 = blockIdx.x * 128;
    const int h  = blockIdx.y;
    const int b  = blockIdx.z;

    const size_t hbase = ((size_t)(b*NH + h)) * SEQ * HD;
    const float* qg = g_q + hbase;
    const float* kg = g_k + hbase;
    const float* vg = g_v + hbase;
    const float* mp = mask + (size_t)b * SEQ;

    const int krow = tid >> 2;
    const int koff = (tid & 3) * 16;
    const int vs  = (tid & 31) + 32 * ((tid >> 5) & 1);
    const int vd0 = (tid >> 6) * 16;

    {
        const int qr = tid >> 1;
        const int qc = (tid & 1) * 32;
        const float* qp = qg + (size_t)(q0 + qr) * HD + qc;
        #pragma unroll
        for (int j = 0; j < 8; j++) {
            float4 v = *(const float4*)(qp + j * 4);
            float* p = &Qs[qr * 68 + qc + j * 4];
            p[0]=f_tf32(v.x); p[1]=f_tf32(v.y); p[2]=f_tf32(v.z); p[3]=f_tf32(v.w);
        }
    }

    float4 kr[4], vr[4];
    float mkr;
    #pragma unroll
    for (int j = 0; j < 4; j++) {
        kr[j] = *(const float4*)(kg + (size_t)krow * HD + koff + j * 4);
        vr[j] = *(const float4*)(vg + (size_t)vs * HD + vd0 + j * 4);
    }
    mkr = (tid < 64) ? mp[tid] : 0.f;

    float co[8][4];
    #pragma unroll
    for (int t = 0; t < 8; t++)
        #pragma unroll
        for (int e = 0; e < 4; e++) co[t][e] = 0.f;
    float lR[2] = { 0.f, 0.f };

    for (int t = 0; t < 32; t++) {
        const int tn = (t < 31) ? t + 1 : 31;
        __syncthreads();

        #pragma unroll
        for (int j = 0; j < 4; j++) {
            float* p = &Ks[krow * 68 + koff + j * 4];
            p[0]=f_tf32(kr[j].x); p[1]=f_tf32(kr[j].y); p[2]=f_tf32(kr[j].z); p[3]=f_tf32(kr[j].w);
        }
        #pragma unroll
        for (int j = 0; j < 4; j++) {
            VT[(vd0 + j*4 + 0) * 68 + vs] = f_tf32(vr[j].x);
            VT[(vd0 + j*4 + 1) * 68 + vs] = f_tf32(vr[j].y);
            VT[(vd0 + j*4 + 2) * 68 + vs] = f_tf32(vr[j].z);
            VT[(vd0 + j*4 + 3) * 68 + vs] = f_tf32(vr[j].w);
        }
        if (tid < 64) msk[tid] = mkr;
        __syncthreads();

        #pragma unroll
        for (int j = 0; j < 4; j++)
            kr[j] = *(const float4*)(kg + (size_t)(tn*64 + krow) * HD + koff + j * 4);
        mkr = (tid < 64) ? mp[tn*64 + tid] : 0.f;

        // ---- S = Q K^T ----
        float cs[8][4];
        #pragma unroll
        for (int tt = 0; tt < 8; tt++)
            #pragma unroll
            for (int e = 0; e < 4; e++) cs[tt][e] = 0.f;
        #pragma unroll
        for (int k8 = 0; k8 < 8; k8++) {
            const int kc = k8 * 8 + tig;
            uint32_t a[4];
            a[0] = fbits(Qs[(r0 + gid) * 68 + kc]);
            a[1] = fbits(Qs[(r0 + 8 + gid) * 68 + kc]);
            a[2] = fbits(Qs[(r0 + gid) * 68 + kc + 4]);
            a[3] = fbits(Qs[(r0 + 8 + gid) * 68 + kc + 4]);
            uint32_t bf[8][2];
            #pragma unroll
            for (int tt = 0; tt < 8; tt++) {
                const int n = tt * 8 + gid;
                bf[tt][0] = fbits(Ks[n * 68 + kc]);
                bf[tt][1] = fbits(Ks[n * 68 + kc + 4]);
            }
            #pragma unroll
            for (int tt = 0; tt < 8; tt++)
                mma8(cs[tt], a, bf[tt]);
        }

        // ---- softmax numerator (no max shift; scores bounded) ----
        #pragma unroll
        for (int j = 0; j < 2; j++) {
            const int rbase = r0 + j * 8 + gid;
            #pragma unroll
            for (int tt = 0; tt < 8; tt++) {
                float p0 = __expf(fmaf(cs[tt][j*2],   0.125f, msk[tt*8 + 2*tig]));
                float p1 = __expf(fmaf(cs[tt][j*2+1], 0.125f, msk[tt*8 + 2*tig + 1]));
                lR[j] += p0 + p1;
                *(float2*)&Ps[rbase * 68 + tt * 8 + 2 * tig] =
                    make_float2(f_tf32(p0), f_tf32(p1));
            }
        }

        #pragma unroll
        for (int j = 0; j < 4; j++)
            vr[j] = *(const float4*)(vg + (size_t)(tn*64 + vs) * HD + vd0 + j * 4);

        __syncwarp();

        // ---- O += P V ----
        #pragma unroll
        for (int k8 = 0; k8 < 8; k8++) {
            const int kc = k8 * 8 + tig;
            uint32_t a[4];
            a[0] = fbits(Ps[(r0 + gid) * 68 + kc]);
            a[1] = fbits(Ps[(r0 + 8 + gid) * 68 + kc]);
            a[2] = fbits(Ps[(r0 + gid) * 68 + kc + 4]);
            a[3] = fbits(Ps[(r0 + 8 + gid) * 68 + kc + 4]);
            uint32_t bf[8][2];
            #pragma unroll
            for (int tt = 0; tt < 8; tt++) {
                const int n = tt * 8 + gid;
                bf[tt][0] = fbits(VT[n * 68 + kc]);
                bf[tt][1] = fbits(VT[n * 68 + kc + 4]);
            }
            #pragma unroll
            for (int tt = 0; tt < 8; tt++)
                mma8(co[tt], a, bf[tt]);
        }
    }

    #pragma unroll
    for (int j = 0; j < 2; j++) {
        lR[j] += __shfl_xor_sync(0xffffffffu, lR[j], 1);
        lR[j] += __shfl_xor_sync(0xffffffffu, lR[j], 2);
        const float invl = 1.0f / lR[j];
        const int row = r0 + j * 8 + gid;
        const int s = q0 + row;
        float* po = &out[((size_t)(b * SEQ + s)) * EMB + h * HD];
        #pragma unroll
        for (int tt = 0; tt < 8; tt++) {
            *(float2*)(po + tt * 8 + 2 * tig) =
                make_float2(co[tt][j*2] * invl, co[tt][j*2+1] * invl);
        }
    }
}

// ---------------------------------------------------------------------------
extern "C" void kernel_launch(void* const* d_in, const int* in_sizes, int n_in,
                              void* d_out, int out_size)
{
    const float* x    = (const float*)d_in[0];
    const float* mask = (const float*)d_in[1];
    const float* Wq   = (const float*)d_in[2];
    const float* bq   = (const float*)d_in[3];
    const float* Wk   = (const float*)d_in[4];
    const float* bk   = (const float*)d_in[5];
    const float* Wv   = (const float*)d_in[6];
    const float* bv   = (const float*)d_in[7];
    float* out = (float*)d_out;

    const int gemm_smem  = 18432 * (int)sizeof(float);   // 73728 B
    const int flash_smem = 26176 * (int)sizeof(float);   // 104704 B
    cudaFuncSetAttribute(qkv_gemm_mma, cudaFuncAttributeMaxDynamicSharedMemorySize, gemm_smem);
    cudaFuncSetAttribute(flash_mma,    cudaFuncAttributeMaxDynamicSharedMemorySize, flash_smem);

    rope_table<<<(SEQ*32 + 255)/256, 256>>>();

    dim3 ggrid(EMB/128, MTOT/128, 3);
    qkv_gemm_mma<<<ggrid, 256, gemm_smem>>>(x, Wq, bq, Wk, bk, Wv, bv);

    dim3 fgrid(SEQ/128, NH, BATCH);
    flash_mma<<<fgrid, 256, flash_smem>>>(mask, out);
}

// round 16
// speedup vs baseline: 1.1567x; 1.0311x over previous
#include <cuda_runtime.h>
#include <math.h>
#include <stdint.h>

#define BATCH 2
#define SEQ   2048
#define NH    16
#define HD    64
#define EMB   1024
#define MTOT  (BATCH*SEQ)

static __device__ float g_q[BATCH*NH*SEQ*HD];
static __device__ float g_k[BATCH*NH*SEQ*HD];
static __device__ float g_v[BATCH*NH*SEQ*HD];
static __device__ float g_rope[SEQ*64];   // [s][0..31]=cos, [s][32..63]=sin

__device__ __forceinline__ uint32_t cvt_tf32(float f) {
    uint32_t r; asm("cvt.rna.tf32.f32 %0, %1;" : "=r"(r) : "f"(f)); return r;
}
__device__ __forceinline__ float f_tf32(float f) { return __uint_as_float(cvt_tf32(f)); }
__device__ __forceinline__ uint32_t fbits(float f) { return __float_as_uint(f); }

__device__ __forceinline__ void mma8(float c[4], const uint32_t a[4], const uint32_t b[2]) {
    asm volatile(
        "mma.sync.aligned.m16n8k8.row.col.f32.tf32.tf32.f32 "
        "{%0,%1,%2,%3}, {%4,%5,%6,%7}, {%8,%9}, {%0,%1,%2,%3};"
        : "+f"(c[0]), "+f"(c[1]), "+f"(c[2]), "+f"(c[3])
        : "r"(a[0]), "r"(a[1]), "r"(a[2]), "r"(a[3]), "r"(b[0]), "r"(b[1]));
}

__device__ __forceinline__ void cp16(uint32_t smem_addr, const void* gptr) {
    asm volatile("cp.async.ca.shared.global [%0], [%1], 16;"
                 :: "r"(smem_addr), "l"(gptr));
}
#define CP_COMMIT() asm volatile("cp.async.commit_group;" ::: "memory")
#define CP_WAIT1()  asm volatile("cp.async.wait_group 1;" ::: "memory")

// ---------------------------------------------------------------------------
// QKV GEMM v5 (R12-proven, FROZEN): 128x128 CTA, 256 thr, warp tile 32x64,
// K-chunks 32, 2-stage cp.async, tf32 at fragment load, fused RoPE epilogue.
// ---------------------------------------------------------------------------
__global__ __launch_bounds__(256, 2) void qkv_gemm_mma(
    const float* __restrict__ X,
    const float* __restrict__ Wq, const float* __restrict__ bq,
    const float* __restrict__ Wk, const float* __restrict__ bk,
    const float* __restrict__ Wv, const float* __restrict__ bv)
{
    const float *W, *bias; float* out;
    if (blockIdx.z == 0)      { W = Wq; bias = bq; out = g_q; }
    else if (blockIdx.z == 1) { W = Wk; bias = bk; out = g_k; }
    else                      { W = Wv; bias = bv; out = g_v; }
    const bool do_rope = (blockIdx.z != 2);

    extern __shared__ float sh[];
    float* As[2] = { sh,        sh + 4608 };
    float* Bs[2] = { sh + 9216, sh + 13824 };

    const int tid  = threadIdx.x;
    const int lane = tid & 31;
    const int wid  = tid >> 5;
    const int gid  = lane >> 2;
    const int tig  = lane & 3;
    const int wm   = wid & 3;
    const int wn   = wid >> 2;
    const int m0 = blockIdx.y * 128;
    const int n0 = blockIdx.x * 128;

    const int lr = tid >> 1;
    const int lc = (tid & 1) * 16;
    const float* ag = X + (size_t)(m0 + lr) * EMB + lc;
    const float* bg = W + (size_t)(n0 + lr) * EMB + lc;

    const uint32_t sa[2] = { (uint32_t)__cvta_generic_to_shared(&As[0][lr*36 + lc]),
                             (uint32_t)__cvta_generic_to_shared(&As[1][lr*36 + lc]) };
    const uint32_t sb[2] = { (uint32_t)__cvta_generic_to_shared(&Bs[0][lr*36 + lc]),
                             (uint32_t)__cvta_generic_to_shared(&Bs[1][lr*36 + lc]) };

    float acc[2][8][4];
    #pragma unroll
    for (int i = 0; i < 2; i++)
        #pragma unroll
        for (int t = 0; t < 8; t++)
            #pragma unroll
            for (int e = 0; e < 4; e++) acc[i][t][e] = 0.f;

    #pragma unroll
    for (int j = 0; j < 4; j++) {
        cp16(sa[0] + j*16, ag + j*4);
        cp16(sb[0] + j*16, bg + j*4);
    }
    CP_COMMIT();
    #pragma unroll
    for (int j = 0; j < 4; j++) {
        cp16(sa[1] + j*16, ag + 32 + j*4);
        cp16(sb[1] + j*16, bg + 32 + j*4);
    }
    CP_COMMIT();

    for (int c = 0; c < 32; c++) {
        const int buf = c & 1;
        CP_WAIT1();
        __syncthreads();

        const float* A = As[buf];
        const float* B = Bs[buf];
        #pragma unroll
        for (int k8 = 0; k8 < 4; k8++) {
            const int kc = k8 * 8 + tig;
            uint32_t a[2][4];
            #pragma unroll
            for (int i = 0; i < 2; i++) {
                const int r = wm * 32 + i * 16 + gid;
                a[i][0] = cvt_tf32(A[r * 36 + kc]);
                a[i][1] = cvt_tf32(A[(r + 8) * 36 + kc]);
                a[i][2] = cvt_tf32(A[r * 36 + kc + 4]);
                a[i][3] = cvt_tf32(A[(r + 8) * 36 + kc + 4]);
            }
            uint32_t b[8][2];
            #pragma unroll
            for (int t = 0; t < 8; t++) {
                const int n = wn * 64 + t * 8 + gid;
                b[t][0] = cvt_tf32(B[n * 36 + kc]);
                b[t][1] = cvt_tf32(B[n * 36 + kc + 4]);
            }
            #pragma unroll
            for (int i = 0; i < 2; i++)
                #pragma unroll
                for (int t = 0; t < 8; t++)
                    mma8(acc[i][t], a[i], b[t]);
        }
        __syncthreads();
        if (c < 30) {
            const int nc = (c + 2) * 32;
            #pragma unroll
            for (int j = 0; j < 4; j++) {
                cp16(sa[buf] + j*16, ag + nc + j*4);
                cp16(sb[buf] + j*16, bg + nc + j*4);
            }
        }
        CP_COMMIT();
    }

    if (do_rope) {
        #pragma unroll
        for (int i = 0; i < 2; i++) {
            const int m = m0 + wm * 32 + i * 16 + gid;
            const int bb = m >> 11;
            const int s  = m & 2047;
            const float* rp0 = &g_rope[(size_t)s * 64];
            const float* rp1 = &g_rope[(size_t)(s + 8) * 64];
            #pragma unroll
            for (int t = 0; t < 4; t++) {
                const int n  = n0 + wn * 64 + t * 8 + 2 * tig;
                const int h  = n >> 6, dd = n & 63;
                const float bl0 = bias[n],      bl1 = bias[n + 1];
                const float bh0 = bias[n + 32], bh1 = bias[n + 33];
                const float lo0 = acc[i][t][0] + bl0,   lo1 = acc[i][t][1] + bl1;
                const float hi0 = acc[i][t+4][0] + bh0, hi1 = acc[i][t+4][1] + bh1;
                const float c0 = rp0[dd], c1 = rp0[dd + 1];
                const float s0 = rp0[32 + dd], s1 = rp0[32 + dd + 1];
                float* po = &out[(((size_t)(bb * NH + h)) * SEQ + s) * HD + dd];
                *(float2*)po        = make_float2(lo0 * c0 - hi0 * s0, lo1 * c1 - hi1 * s1);
                *(float2*)(po + 32) = make_float2(hi0 * c0 + lo0 * s0, hi1 * c1 + lo1 * s1);
                const float lo2 = acc[i][t][2] + bl0,   lo3 = acc[i][t][3] + bl1;
                const float hi2 = acc[i][t+4][2] + bh0, hi3 = acc[i][t+4][3] + bh1;
                const float d0 = rp1[dd], d1 = rp1[dd + 1];
                const float e0 = rp1[32 + dd], e1 = rp1[32 + dd + 1];
                float* po2 = po + 8 * HD;
                *(float2*)po2        = make_float2(lo2 * d0 - hi2 * e0, lo3 * d1 - hi3 * e1);
                *(float2*)(po2 + 32) = make_float2(hi2 * d0 + lo2 * e0, hi3 * d1 + lo3 * e1);
            }
        }
    } else {
        #pragma unroll
        for (int i = 0; i < 2; i++) {
            const int m = m0 + wm * 32 + i * 16 + gid;
            const int bb = m >> 11;
            const int s  = m & 2047;
            #pragma unroll
            for (int t = 0; t < 8; t++) {
                const int n = n0 + wn * 64 + t * 8 + 2 * tig;
                const int h = n >> 6, dd = n & 63;
                const float b0v = bias[n], b1v = bias[n + 1];
                float* po = &out[(((size_t)(bb * NH + h)) * SEQ + s) * HD + dd];
                *(float2*)po = make_float2(acc[i][t][0] + b0v, acc[i][t][1] + b1v);
                float* po2 = po + 8 * HD;
                *(float2*)po2 = make_float2(acc[i][t][2] + b0v, acc[i][t][3] + b1v);
            }
        }
    }
}

// ---------------------------------------------------------------------------
// RoPE table build.
// ---------------------------------------------------------------------------
__global__ void rope_table()
{
    int idx = blockIdx.x * blockDim.x + threadIdx.x;
    if (idx >= SEQ * 32) return;
    const int s = idx >> 5, i = idx & 31;
    const float inv = expf(-(float)i * (logf(10000.0f) / 32.0f));
    float sn, cs;
    sincosf((float)s * inv, &sn, &cs);
    g_rope[s * 64 + i]      = cs;
    g_rope[s * 64 + 32 + i] = sn;
}

// ---------------------------------------------------------------------------
// Flash attention v7: CTA = (b, h, 128 q-rows), 256 thr / 8 warps in a
// 4x2 grid: warp (wm, wn) owns rows 32*wm x cols 32*wn of S (32x32 tiles).
// Halves b-fragment duplication vs 16x64 tiles while keeping 8 warps.
// No-max softmax; partial row sums combined across the wn-pair at the end.
// Pairwise bar.sync(wm+1, 64) orders P writes vs PV reads.
// smem: Qs 8704, Ks 4352, VT 4352, Ps 8704, msk 64, lbuf 256 = 26432 floats.
// ---------------------------------------------------------------------------
__global__ __launch_bounds__(256, 2) void flash_mma(const float* __restrict__ mask,
                                                    float* __restrict__ out)
{
    extern __shared__ float sh[];
    float* Qs   = sh;            // 128 x 68
    float* Ks   = sh + 8704;     // 64 x 68
    float* VT   = sh + 13056;    // 64 x 68
    float* Ps   = sh + 17408;    // 128 x 68
    float* msk  = sh + 26112;    // 64
    float* lbuf = sh + 26176;    // 2 x 128 partial row sums

    const int tid  = threadIdx.x;
    const int lane = tid & 31;
    const int wid  = tid >> 5;
    const int gid  = lane >> 2;
    const int tig  = lane & 3;
    const int wm   = wid & 3;       // row band
    const int wn   = wid >> 2;      // col band
    const int r0   = wm * 32;
    const int c0   = wn * 32;
    const int q0 = blockIdx.x * 128;
    const int h  = blockIdx.y;
    const int b  = blockIdx.z;

    const size_t hbase = ((size_t)(b*NH + h)) * SEQ * HD;
    const float* qg = g_q + hbase;
    const float* kg = g_k + hbase;
    const float* vg = g_v + hbase;
    const float* mp = mask + (size_t)b * SEQ;

    const int krow = tid >> 2;
    const int koff = (tid & 3) * 16;
    const int vs  = (tid & 31) + 32 * ((tid >> 5) & 1);
    const int vd0 = (tid >> 6) * 16;

    {
        const int qr = tid >> 1;
        const int qc = (tid & 1) * 32;
        const float* qp = qg + (size_t)(q0 + qr) * HD + qc;
        #pragma unroll
        for (int j = 0; j < 8; j++) {
            float4 v = *(const float4*)(qp + j * 4);
            float* p = &Qs[qr * 68 + qc + j * 4];
            p[0]=f_tf32(v.x); p[1]=f_tf32(v.y); p[2]=f_tf32(v.z); p[3]=f_tf32(v.w);
        }
    }

    float4 kr[4], vr[4];
    float mkr;
    #pragma unroll
    for (int j = 0; j < 4; j++) {
        kr[j] = *(const float4*)(kg + (size_t)krow * HD + koff + j * 4);
        vr[j] = *(const float4*)(vg + (size_t)vs * HD + vd0 + j * 4);
    }
    mkr = (tid < 64) ? mp[tid] : 0.f;

    float co[2][4][4];
    #pragma unroll
    for (int i = 0; i < 2; i++)
        #pragma unroll
        for (int t = 0; t < 4; t++)
            #pragma unroll
            for (int e = 0; e < 4; e++) co[i][t][e] = 0.f;
    float lR[2][2] = { {0.f, 0.f}, {0.f, 0.f} };

    for (int t = 0; t < 32; t++) {
        const int tn = (t < 31) ? t + 1 : 31;
        __syncthreads();

        #pragma unroll
        for (int j = 0; j < 4; j++) {
            float* p = &Ks[krow * 68 + koff + j * 4];
            p[0]=f_tf32(kr[j].x); p[1]=f_tf32(kr[j].y); p[2]=f_tf32(kr[j].z); p[3]=f_tf32(kr[j].w);
        }
        #pragma unroll
        for (int j = 0; j < 4; j++) {
            VT[(vd0 + j*4 + 0) * 68 + vs] = f_tf32(vr[j].x);
            VT[(vd0 + j*4 + 1) * 68 + vs] = f_tf32(vr[j].y);
            VT[(vd0 + j*4 + 2) * 68 + vs] = f_tf32(vr[j].z);
            VT[(vd0 + j*4 + 3) * 68 + vs] = f_tf32(vr[j].w);
        }
        if (tid < 64) msk[tid] = mkr;
        __syncthreads();

        #pragma unroll
        for (int j = 0; j < 4; j++)
            kr[j] = *(const float4*)(kg + (size_t)(tn*64 + krow) * HD + koff + j * 4);
        mkr = (tid < 64) ? mp[tn*64 + tid] : 0.f;

        // ---- S = Q K^T : warp computes rows r0..r0+31 x cols c0..c0+31 ----
        float cs[2][4][4];
        #pragma unroll
        for (int i = 0; i < 2; i++)
            #pragma unroll
            for (int tt = 0; tt < 4; tt++)
                #pragma unroll
                for (int e = 0; e < 4; e++) cs[i][tt][e] = 0.f;
        #pragma unroll
        for (int k8 = 0; k8 < 8; k8++) {
            const int kc = k8 * 8 + tig;
            uint32_t a[2][4];
            #pragma unroll
            for (int i = 0; i < 2; i++) {
                const int r = r0 + i * 16 + gid;
                a[i][0] = fbits(Qs[r * 68 + kc]);
                a[i][1] = fbits(Qs[(r + 8) * 68 + kc]);
                a[i][2] = fbits(Qs[r * 68 + kc + 4]);
                a[i][3] = fbits(Qs[(r + 8) * 68 + kc + 4]);
            }
            uint32_t bf[4][2];
            #pragma unroll
            for (int tt = 0; tt < 4; tt++) {
                const int n = c0 + tt * 8 + gid;
                bf[tt][0] = fbits(Ks[n * 68 + kc]);
                bf[tt][1] = fbits(Ks[n * 68 + kc + 4]);
            }
            #pragma unroll
            for (int i = 0; i < 2; i++)
                #pragma unroll
                for (int tt = 0; tt < 4; tt++)
                    mma8(cs[i][tt], a[i], bf[tt]);
        }

        // ---- softmax numerator on this warp's 32-col band ----
        #pragma unroll
        for (int i = 0; i < 2; i++) {
            #pragma unroll
            for (int j = 0; j < 2; j++) {
                const int rbase = r0 + i * 16 + j * 8 + gid;
                #pragma unroll
                for (int tt = 0; tt < 4; tt++) {
                    const int col = c0 + tt * 8 + 2 * tig;
                    float p0 = __expf(fmaf(cs[i][tt][j*2],   0.125f, msk[col]));
                    float p1 = __expf(fmaf(cs[i][tt][j*2+1], 0.125f, msk[col + 1]));
                    lR[i][j] += p0 + p1;
                    *(float2*)&Ps[rbase * 68 + col] =
                        make_float2(f_tf32(p0), f_tf32(p1));
                }
            }
        }

        #pragma unroll
        for (int j = 0; j < 4; j++)
            vr[j] = *(const float4*)(vg + (size_t)(tn*64 + vs) * HD + vd0 + j * 4);

        // P rows r0..r0+31 are written by the wn-pair (wm, wm+4): sync them.
        asm volatile("bar.sync %0, 64;" :: "r"(wm + 1) : "memory");

        // ---- O += P V : warp computes rows r0..+31 x d-cols c0..+31 ----
        #pragma unroll
        for (int k8 = 0; k8 < 8; k8++) {
            const int kc = k8 * 8 + tig;
            uint32_t a[2][4];
            #pragma unroll
            for (int i = 0; i < 2; i++) {
                const int r = r0 + i * 16 + gid;
                a[i][0] = fbits(Ps[r * 68 + kc]);
                a[i][1] = fbits(Ps[(r + 8) * 68 + kc]);
                a[i][2] = fbits(Ps[r * 68 + kc + 4]);
                a[i][3] = fbits(Ps[(r + 8) * 68 + kc + 4]);
            }
            uint32_t bf[4][2];
            #pragma unroll
            for (int tt = 0; tt < 4; tt++) {
                const int n = c0 + tt * 8 + gid;
                bf[tt][0] = fbits(VT[n * 68 + kc]);
                bf[tt][1] = fbits(VT[n * 68 + kc + 4]);
            }
            #pragma unroll
            for (int i = 0; i < 2; i++)
                #pragma unroll
                for (int tt = 0; tt < 4; tt++)
                    mma8(co[i][tt], a[i], bf[tt]);
        }
    }

    // ---- combine partial row sums across the wn-pair ----
    #pragma unroll
    for (int i = 0; i < 2; i++) {
        #pragma unroll
        for (int j = 0; j < 2; j++) {
            lR[i][j] += __shfl_xor_sync(0xffffffffu, lR[i][j], 1);
            lR[i][j] += __shfl_xor_sync(0xffffffffu, lR[i][j], 2);
            if (tig == 0)
                lbuf[wn * 128 + r0 + i * 16 + j * 8 + gid] = lR[i][j];
        }
    }
    __syncthreads();

    #pragma unroll
    for (int i = 0; i < 2; i++) {
        #pragma unroll
        for (int j = 0; j < 2; j++) {
            const int row = r0 + i * 16 + j * 8 + gid;
            const float invl = 1.0f / (lbuf[row] + lbuf[128 + row]);
            const int s = q0 + row;
            float* po = &out[((size_t)(b * SEQ + s)) * EMB + h * HD + c0];
            #pragma unroll
            for (int tt = 0; tt < 4; tt++) {
                *(float2*)(po + tt * 8 + 2 * tig) =
                    make_float2(co[i][tt][j*2] * invl, co[i][tt][j*2+1] * invl);
            }
        }
    }
}

// ---------------------------------------------------------------------------
extern "C" void kernel_launch(void* const* d_in, const int* in_sizes, int n_in,
                              void* d_out, int out_size)
{
    const float* x    = (const float*)d_in[0];
    const float* mask = (const float*)d_in[1];
    const float* Wq   = (const float*)d_in[2];
    const float* bq   = (const float*)d_in[3];
    const float* Wk   = (const float*)d_in[4];
    const float* bk   = (const float*)d_in[5];
    const float* Wv   = (const float*)d_in[6];
    const float* bv   = (const float*)d_in[7];
    float* out = (float*)d_out;

    const int gemm_smem  = 18432 * (int)sizeof(float);   // 73728 B
    const int flash_smem = 26432 * (int)sizeof(float);   // 105728 B
    cudaFuncSetAttribute(qkv_gemm_mma, cudaFuncAttributeMaxDynamicSharedMemorySize, gemm_smem);
    cudaFuncSetAttribute(flash_mma,    cudaFuncAttributeMaxDynamicSharedMemorySize, flash_smem);

    rope_table<<<(SEQ*32 + 255)/256, 256>>>();

    dim3 ggrid(EMB/128, MTOT/128, 3);
    qkv_gemm_mma<<<ggrid, 256, gemm_smem>>>(x, Wq, bq, Wk, bk, Wv, bv);

    dim3 fgrid(SEQ/128, NH, BATCH);
    flash_mma<<<fgrid, 256, flash_smem>>>(mask, out);
}